// round 6
// baseline (speedup 1.0000x reference)
#include <cuda_runtime.h>
#include <cstdint>

// Skeleton forward kinematics: 6d rotations -> world-space joint positions.
// angles: [B, 16, 6] f32   xyz: [1, 16, 3] f32   out: [B, 16, 3] f32
//
// Round-6: persistent warps, per-warp DOUBLE-BUFFERED cp.async pipeline.
// Each warp owns two private smem strips ([24 rows][33 cols] float4). While
// computing tile i from strip A it prefetches tile i+1 into strip B
// (cp.async groups, wait_group 1). Only __syncwarp -- warps never couple.

namespace {

constexpr int NJ    = 16;
constexpr int WPB   = 2;                 // warps per block
constexpr int TPB   = 32 * WPB;          // 64 threads
constexpr int WPIT  = 33;                // per-strip float4 pitch (odd)
constexpr int STRIP = 24 * WPIT;         // float4s per strip
constexpr size_t SMEM_BYTES =
    (size_t)WPB * 2 * STRIP * sizeof(float4) + (size_t)WPB * 48 * sizeof(float);
constexpr int GRID = 608;                // 4 blocks/SM x 152 SMs (one wave)

__device__ __forceinline__ void rot6d(const float* __restrict__ a, float R[9]) {
    float n1 = rsqrtf(a[0] * a[0] + a[1] * a[1] + a[2] * a[2]);
    float b1x = a[0] * n1, b1y = a[1] * n1, b1z = a[2] * n1;
    float d = b1x * a[3] + b1y * a[4] + b1z * a[5];
    float b2x = a[3] - d * b1x, b2y = a[4] - d * b1y, b2z = a[5] - d * b1z;
    float n2 = rsqrtf(b2x * b2x + b2y * b2y + b2z * b2z);
    b2x *= n2; b2y *= n2; b2z *= n2;
    R[0] = b1x; R[1] = b1y; R[2] = b1z;
    R[3] = b2x; R[4] = b2y; R[5] = b2z;
    R[6] = b1y * b2z - b1z * b2y;
    R[7] = b1z * b2x - b1x * b2z;
    R[8] = b1x * b2y - b1y * b2x;
}

__device__ __forceinline__ void stage_async(float4* __restrict__ strip,
                                            const float4* __restrict__ angles4,
                                            size_t eBase, int l) {
    const float4* __restrict__ src = angles4 + eBase * 24;
#pragma unroll
    for (int k = 0; k < 24; ++k) {
        int g = l + k * 32;                  // 0..767
        int b = g / 24;
        int r = g - b * 24;
        uint32_t saddr = (uint32_t)__cvta_generic_to_shared(strip + r * WPIT + b);
        asm volatile("cp.async.cg.shared.global [%0], [%1], 16;"
                     :: "r"(saddr), "l"(src + g) : "memory");
    }
    asm volatile("cp.async.commit_group;" ::: "memory");
}

__device__ __forceinline__ void compute_tile(float4* __restrict__ strip,
                                             const float* __restrict__ sref,
                                             int l) {
    float a2[12];
    float pw[48];
    float Rc[9], Rs[9];

    auto loadPair = [&](int j) {
        float4 q0 = strip[(3 * j + 0) * WPIT + l];
        float4 q1 = strip[(3 * j + 1) * WPIT + l];
        float4 q2 = strip[(3 * j + 2) * WPIT + l];
        a2[0] = q0.x; a2[1] = q0.y; a2[2]  = q0.z; a2[3]  = q0.w;
        a2[4] = q1.x; a2[5] = q1.y; a2[6]  = q1.z; a2[7]  = q1.w;
        a2[8] = q2.x; a2[9] = q2.y; a2[10] = q2.z; a2[11] = q2.w;
    };
    auto flushRow = [&](int r) {
        strip[r * WPIT + l] = make_float4(pw[4 * r + 0], pw[4 * r + 1],
                                          pw[4 * r + 2], pw[4 * r + 3]);
    };
    auto step = [&](int p, int c, int ao) {
        float R[9];
        rot6d(&a2[ao], R);
        float tx = sref[3 * c + 0] - sref[3 * p + 0];
        float ty = sref[3 * c + 1] - sref[3 * p + 1];
        float tz = sref[3 * c + 2] - sref[3 * p + 2];
        float ltx = R[0] * tx + R[1] * ty + R[2] * tz;
        float lty = R[3] * tx + R[4] * ty + R[5] * tz;
        float ltz = R[6] * tx + R[7] * ty + R[8] * tz;
        float Rn[9];
#pragma unroll
        for (int i = 0; i < 3; ++i)
#pragma unroll
            for (int k = 0; k < 3; ++k)
                Rn[3 * i + k] = Rc[3 * i + 0] * R[0 + k]
                              + Rc[3 * i + 1] * R[3 + k]
                              + Rc[3 * i + 2] * R[6 + k];
        pw[3 * c + 0] = Rc[0] * ltx + Rc[1] * lty + Rc[2] * ltz + pw[3 * p + 0];
        pw[3 * c + 1] = Rc[3] * ltx + Rc[4] * lty + Rc[5] * ltz + pw[3 * p + 1];
        pw[3 * c + 2] = Rc[6] * ltx + Rc[7] * lty + Rc[8] * ltz + pw[3 * p + 2];
#pragma unroll
        for (int i = 0; i < 9; ++i) Rc[i] = Rn[i];
    };

    // Root joint 0
    loadPair(0);
    rot6d(&a2[0], Rc);
    {
        float x = sref[0], y = sref[1], z = sref[2];
        pw[0] = Rc[0] * x + Rc[1] * y + Rc[2] * z;
        pw[1] = Rc[3] * x + Rc[4] * y + Rc[5] * z;
        pw[2] = Rc[6] * x + Rc[7] * y + Rc[8] * z;
    }

    // Chain 0-1-2-3 (flush row r only after its angle floats are consumed)
    step(0, 1, 6);  flushRow(0);
    loadPair(1);
    step(1, 2, 0);  flushRow(1);
    step(2, 3, 6);  flushRow(2);
#pragma unroll
    for (int i = 0; i < 9; ++i) Rs[i] = Rc[i];

    // Branch A: 3-4-5
    loadPair(2);
    step(3, 4, 0);
    step(4, 5, 6);  flushRow(3);

    // Branch B: 3-6-7-8-9-10
#pragma unroll
    for (int i = 0; i < 9; ++i) Rc[i] = Rs[i];
    loadPair(3);
    step(3, 6, 0);  flushRow(4);
    step(6, 7, 6);  flushRow(5);
    loadPair(4);
    step(7, 8, 0);
    step(8, 9, 6);  flushRow(6);
    loadPair(5);
    step(9, 10, 0); flushRow(7);

    // Branch C: 3-11-12-13-14-15
#pragma unroll
    for (int i = 0; i < 9; ++i) Rc[i] = Rs[i];
    step(3, 11, 6);  flushRow(8);
    loadPair(6);
    step(11, 12, 0);
    step(12, 13, 6); flushRow(9);
    loadPair(7);
    step(13, 14, 0); flushRow(10);
    step(14, 15, 6); flushRow(11);
}

__device__ __forceinline__ void gather_tile(const float4* __restrict__ strip,
                                            float4* __restrict__ out4,
                                            size_t eBase, int l) {
    float4* __restrict__ dst = out4 + eBase * 12;
#pragma unroll
    for (int k = 0; k < 12; ++k) {
        int g = l + k * 32;                  // 0..383
        int b = g / 12;
        int r = g - b * 12;
        dst[g] = strip[r * WPIT + b];
    }
}

__global__ __launch_bounds__(TPB)
void skeleton_fk_v6(const float4* __restrict__ angles4,
                    const float*  __restrict__ xyz,
                    float4* __restrict__ out4,
                    int numWarpTiles)
{
    extern __shared__ float4 smem[];
    const int l = threadIdx.x & 31;
    const int w = threadIdx.x >> 5;

    float4* __restrict__ s0 = smem + (w * 2 + 0) * STRIP;
    float4* __restrict__ s1 = smem + (w * 2 + 1) * STRIP;
    float*  __restrict__ sref =
        reinterpret_cast<float*>(smem + WPB * 2 * STRIP) + w * 48;

    if (l < 16) {
        sref[l]      = __ldg(xyz + l);
        sref[l + 16] = __ldg(xyz + l + 16);
        sref[l + 32] = __ldg(xyz + l + 32);
    }
    __syncwarp();

    const int warpId     = blockIdx.x * WPB + w;
    const int totalWarps = gridDim.x * WPB;

    int tile = warpId;
    if (tile >= numWarpTiles) return;          // safe: no block barriers

    // Prologue: stage first tile into strip 0.
    stage_async(s0, angles4, (size_t)tile * 32, l);

    int cur = 0;
    for (;;) {
        const int next = tile + totalWarps;
        float4* bufC = cur ? s1 : s0;
        float4* bufN = cur ? s0 : s1;

        if (next < numWarpTiles) {
            stage_async(bufN, angles4, (size_t)next * 32, l);
            asm volatile("cp.async.wait_group 1;" ::: "memory");
        } else {
            asm volatile("cp.async.wait_group 0;" ::: "memory");
        }
        __syncwarp();                          // tile data visible to warp

        compute_tile(bufC, sref, l);
        __syncwarp();                          // pw rows visible to gatherers

        gather_tile(bufC, out4, (size_t)tile * 32, l);

        if (next >= numWarpTiles) break;
        __syncwarp();                          // gathers done before bufC reuse
        tile = next;
        cur ^= 1;
    }
}

// Tail fallback for batch % 32 != 0 (unused for BATCH=262144).
__global__ void skeleton_fk_tail(const float* __restrict__ angles,
                                 const float* __restrict__ xyz,
                                 float* __restrict__ out,
                                 int start, int batch)
{
    int b = start + blockIdx.x * blockDim.x + threadIdx.x;
    if (b >= batch) return;
    const float* ab = angles + (size_t)b * (NJ * 6);
    float ref[NJ * 3];
#pragma unroll
    for (int i = 0; i < NJ * 3; ++i) ref[i] = __ldg(xyz + i);

    float Rw[NJ * 9], pw[NJ * 3];
    {
        float a[6];
#pragma unroll
        for (int k = 0; k < 6; ++k) a[k] = ab[k];
        rot6d(a, &Rw[0]);
        float x = ref[0], y = ref[1], z = ref[2];
        pw[0] = Rw[0] * x + Rw[1] * y + Rw[2] * z;
        pw[1] = Rw[3] * x + Rw[4] * y + Rw[5] * z;
        pw[2] = Rw[6] * x + Rw[7] * y + Rw[8] * z;
    }
    constexpr int PARENT[15] = {0, 1, 2, 3, 4, 3, 6, 7, 8, 9, 3, 11, 12, 13, 14};
#pragma unroll
    for (int e = 0; e < 15; ++e) {
        const int p = PARENT[e], c = e + 1;
        float a[6];
#pragma unroll
        for (int k = 0; k < 6; ++k) a[k] = ab[6 * c + k];
        float R[9]; rot6d(a, R);
        float tx = ref[3 * c + 0] - ref[3 * p + 0];
        float ty = ref[3 * c + 1] - ref[3 * p + 1];
        float tz = ref[3 * c + 2] - ref[3 * p + 2];
        float ltx = R[0] * tx + R[1] * ty + R[2] * tz;
        float lty = R[3] * tx + R[4] * ty + R[5] * tz;
        float ltz = R[6] * tx + R[7] * ty + R[8] * tz;
        const float* pR = &Rw[9 * p];
        float* nR = &Rw[9 * c];
#pragma unroll
        for (int i = 0; i < 3; ++i)
#pragma unroll
            for (int k = 0; k < 3; ++k)
                nR[3 * i + k] = pR[3 * i + 0] * R[k] + pR[3 * i + 1] * R[3 + k]
                              + pR[3 * i + 2] * R[6 + k];
        pw[3 * c + 0] = pR[0] * ltx + pR[1] * lty + pR[2] * ltz + pw[3 * p + 0];
        pw[3 * c + 1] = pR[3] * ltx + pR[4] * lty + pR[5] * ltz + pw[3 * p + 1];
        pw[3 * c + 2] = pR[6] * ltx + pR[7] * lty + pR[8] * ltz + pw[3 * p + 2];
    }
    float* o = out + (size_t)b * (NJ * 3);
#pragma unroll
    for (int i = 0; i < NJ * 3; ++i) o[i] = pw[i];
}

}  // namespace

extern "C" void kernel_launch(void* const* d_in, const int* in_sizes, int n_in,
                              void* d_out, int out_size) {
    const float* angles = (const float*)d_in[0];
    const float* xyz    = (const float*)d_in[1];
    float* out          = (float*)d_out;

    const int batch        = in_sizes[0] / (NJ * 6);
    const int numWarpTiles = batch / 32;

    cudaFuncSetAttribute(skeleton_fk_v6,
                         cudaFuncAttributeMaxDynamicSharedMemorySize,
                         (int)SMEM_BYTES);

    if (numWarpTiles > 0) {
        int warpsNeeded = numWarpTiles;
        int blocksNeeded = (warpsNeeded + WPB - 1) / WPB;
        int grid = blocksNeeded < GRID ? blocksNeeded : GRID;
        skeleton_fk_v6<<<grid, TPB, SMEM_BYTES>>>(
            (const float4*)angles, xyz, (float4*)out, numWarpTiles);
    }
    const int rem = batch - numWarpTiles * 32;
    if (rem > 0) {
        skeleton_fk_tail<<<(rem + 127) / 128, 128>>>(angles, xyz, out,
                                                     numWarpTiles * 32, batch);
    }
}

// round 7
// speedup vs baseline: 1.1856x; 1.1856x over previous
#include <cuda_runtime.h>
#include <cstdint>

// Skeleton forward kinematics: 6d rotations -> world-space joint positions.
// angles: [B, 16, 6] f32   xyz: [1, 16, 3] f32   out: [B, 16, 3] f32
//
// Round-7: v3 shell (128-elem tile, pitch-129 float4 smem, pw flushed into
// consumed rows, coalesced gather) with a rebuilt compute phase:
//  - pw[c] = Rw[c] @ t + pw[p]  (associativity; kills local_t = 9 FMA/joint)
//  - edge vectors t precomputed once into smem (not per thread per step)
//  - three branches (4-5 / 6-10 / 11-15) interleaved SSA-style for 3x chain ILP

namespace {

constexpr int NJ   = 16;
constexpr int TPB  = 128;
constexpr int PIT  = 129;                       // float4 pitch (odd -> conflict-free)
constexpr size_t SMEM_BYTES = 24 * PIT * sizeof(float4) + 48 * sizeof(float);

__device__ __forceinline__ void rot6d(const float* __restrict__ a, float R[9]) {
    float n1 = rsqrtf(a[0] * a[0] + a[1] * a[1] + a[2] * a[2]);
    float b1x = a[0] * n1, b1y = a[1] * n1, b1z = a[2] * n1;
    float d = b1x * a[3] + b1y * a[4] + b1z * a[5];
    float b2x = a[3] - d * b1x, b2y = a[4] - d * b1y, b2z = a[5] - d * b1z;
    float n2 = rsqrtf(b2x * b2x + b2y * b2y + b2z * b2z);
    b2x *= n2; b2y *= n2; b2z *= n2;
    R[0] = b1x; R[1] = b1y; R[2] = b1z;
    R[3] = b2x; R[4] = b2y; R[5] = b2z;
    R[6] = b1y * b2z - b1z * b2y;
    R[7] = b1z * b2x - b1x * b2z;
    R[8] = b1x * b2y - b1y * b2x;
}

// O = P @ N (3x3)
__device__ __forceinline__ void mm(const float P[9], const float N[9], float O[9]) {
#pragma unroll
    for (int i = 0; i < 3; ++i)
#pragma unroll
        for (int k = 0; k < 3; ++k)
            O[3 * i + k] = P[3 * i + 0] * N[0 + k]
                         + P[3 * i + 1] * N[3 + k]
                         + P[3 * i + 2] * N[6 + k];
}

__global__ __launch_bounds__(TPB, 4)
void skeleton_fk_v7(const float4* __restrict__ angles4,
                    const float*  __restrict__ xyz,
                    float4* __restrict__ out4)
{
    extern __shared__ float4 sa4[];                           // [24 * PIT]
    float* stv = reinterpret_cast<float*>(sa4 + 24 * PIT);    // [48]: ref0 + 15 edges

    const int t = threadIdx.x;
    const size_t tile = (size_t)blockIdx.x * TPB;

    // ---- Stage: coalesced LDG.128 -> conflict-free STS.128 ----
    const float4* __restrict__ src = angles4 + tile * 24;
#pragma unroll
    for (int k = 0; k < 24; ++k) {
        int g = t + k * TPB;                 // 0..3071
        int b = g / 24;
        int r = g - b * 24;
        sa4[r * PIT + b] = __ldg(src + g);
    }
    // Edge vectors: stv[0..2] = ref[0]; stv[3+3e+k] = ref[child]-ref[parent].
    {
        constexpr int PARENT[15] = {0, 1, 2, 3, 4, 3, 6, 7, 8, 9, 3, 11, 12, 13, 14};
        if (t < 3) stv[t] = __ldg(xyz + t);
        else if (t < 48) {
            int i = t - 3;
            int e = i / 3, k = i - 3 * e;
            stv[t] = __ldg(xyz + 3 * (e + 1) + k) - __ldg(xyz + 3 * PARENT[e] + k);
        }
    }
    __syncthreads();

    // ---- Compute ----
    {
        auto loadPair = [&](int p, float* a12) {   // joints 2p, 2p+1
            float4 q0 = sa4[(3 * p + 0) * PIT + t];
            float4 q1 = sa4[(3 * p + 1) * PIT + t];
            float4 q2 = sa4[(3 * p + 2) * PIT + t];
            a12[0] = q0.x; a12[1] = q0.y; a12[2]  = q0.z; a12[3]  = q0.w;
            a12[4] = q1.x; a12[5] = q1.y; a12[6]  = q1.z; a12[7]  = q1.w;
            a12[8] = q2.x; a12[9] = q2.y; a12[10] = q2.z; a12[11] = q2.w;
        };
        auto flushRow = [&](int r, float v0, float v1, float v2, float v3) {
            sa4[r * PIT + t] = make_float4(v0, v1, v2, v3);
        };
        // pwc = Rw_child @ tv(edge c-1) + pwp
        auto pwstep = [&](const float Rw[9], int c, const float pwp[3], float pwc[3]) {
            float tx = stv[3 * c + 0];      // == stv[3 + 3*(c-1) + k]
            float ty = stv[3 * c + 1];
            float tz = stv[3 * c + 2];
            pwc[0] = Rw[0] * tx + Rw[1] * ty + Rw[2] * tz + pwp[0];
            pwc[1] = Rw[3] * tx + Rw[4] * ty + Rw[5] * tz + pwp[1];
            pwc[2] = Rw[6] * tx + Rw[7] * ty + Rw[8] * tz + pwp[2];
        };

        // ---- Root chain: joints 0-1-2-3 (rot6d hoisted for ILP) ----
        float a01[12], a23[12];
        loadPair(0, a01);
        loadPair(1, a23);
        float R0[9], R1[9], R2[9], R3[9];
        rot6d(a01 + 0, R0); rot6d(a01 + 6, R1);
        rot6d(a23 + 0, R2); rot6d(a23 + 6, R3);

        float pw0[3], pw1[3], pw2[3], pw3[3];
        {   // pw0 = R0 @ ref0
            float x = stv[0], y = stv[1], z = stv[2];
            pw0[0] = R0[0] * x + R0[1] * y + R0[2] * z;
            pw0[1] = R0[3] * x + R0[4] * y + R0[5] * z;
            pw0[2] = R0[6] * x + R0[7] * y + R0[8] * z;
        }
        float Rw1[9]; mm(R0,  R1, Rw1); pwstep(Rw1, 1, pw0, pw1);
        flushRow(0, pw0[0], pw0[1], pw0[2], pw1[0]);
        float Rw2[9]; mm(Rw1, R2, Rw2); pwstep(Rw2, 2, pw1, pw2);
        flushRow(1, pw1[1], pw1[2], pw2[0], pw2[1]);
        float Rw3[9]; mm(Rw2, R3, Rw3); pwstep(Rw3, 3, pw2, pw3);
        flushRow(2, pw2[2], pw3[0], pw3[1], pw3[2]);

        // ---- Branches A(4-5), B(6-10), C(11-15), interleaved ----
        float a45[12], a67[12], a1011[12];
        loadPair(2, a45);
        loadPair(3, a67);
        loadPair(5, a1011);

        // Round 1: first step of each branch from joint 3.
        float R4[9], R6[9], R11[9];
        rot6d(a45 + 0, R4); rot6d(a67 + 0, R6); rot6d(a1011 + 6, R11);
        float RwA1[9]; mm(Rw3, R4,  RwA1); float pw4[3];  pwstep(RwA1, 4,  pw3, pw4);
        float RwB1[9]; mm(Rw3, R6,  RwB1); float pw6[3];  pwstep(RwB1, 6,  pw3, pw6);
        float RwC1[9]; mm(Rw3, R11, RwC1); float pw11[3]; pwstep(RwC1, 11, pw3, pw11);

        // Round 2.
        float a1213[12];
        loadPair(6, a1213);
        float R5[9], R7[9], R12[9];
        rot6d(a45 + 6, R5); rot6d(a67 + 6, R7); rot6d(a1213 + 0, R12);
        float RwA2[9]; mm(RwA1, R5,  RwA2); float pw5[3];  pwstep(RwA2, 5,  pw4,  pw5);
        flushRow(3, pw4[0], pw4[1], pw4[2], pw5[0]);
        flushRow(4, pw5[1], pw5[2], pw6[0], pw6[1]);
        float RwB2[9]; mm(RwB1, R7,  RwB2); float pw7[3];  pwstep(RwB2, 7,  pw6,  pw7);
        flushRow(5, pw6[2], pw7[0], pw7[1], pw7[2]);
        float RwC2[9]; mm(RwC1, R12, RwC2); float pw12[3]; pwstep(RwC2, 12, pw11, pw12);

        // Round 3.
        float a89[12];
        loadPair(4, a89);
        float R8[9], R13[9];
        rot6d(a89 + 0, R8); rot6d(a1213 + 6, R13);
        float RwB3[9]; mm(RwB2, R8,  RwB3); float pw8[3];  pwstep(RwB3, 8,  pw7,  pw8);
        float RwC3[9]; mm(RwC2, R13, RwC3); float pw13[3]; pwstep(RwC3, 13, pw12, pw13);
        flushRow(9, pw12[0], pw12[1], pw12[2], pw13[0]);

        // Round 4.
        float a1415[12];
        loadPair(7, a1415);
        float R9[9], R14[9];
        rot6d(a89 + 6, R9); rot6d(a1415 + 0, R14);
        float RwB4[9]; mm(RwB3, R9,  RwB4); float pw9[3];  pwstep(RwB4, 9,  pw8,  pw9);
        flushRow(6, pw8[0], pw8[1], pw8[2], pw9[0]);
        float RwC4[9]; mm(RwC3, R14, RwC4); float pw14[3]; pwstep(RwC4, 14, pw13, pw14);
        flushRow(10, pw13[1], pw13[2], pw14[0], pw14[1]);

        // Round 5.
        float R10[9], R15[9];
        rot6d(a1011 + 0, R10); rot6d(a1415 + 6, R15);
        float RwB5[9]; mm(RwB4, R10, RwB5); float pw10[3]; pwstep(RwB5, 10, pw9,  pw10);
        flushRow(7, pw9[1], pw9[2], pw10[0], pw10[1]);
        flushRow(8, pw10[2], pw11[0], pw11[1], pw11[2]);
        float RwC5[9]; mm(RwC4, R15, RwC5); float pw15[3]; pwstep(RwC5, 15, pw14, pw15);
        flushRow(11, pw14[2], pw15[0], pw15[1], pw15[2]);
    }

    __syncthreads();

    // ---- Gather: conflict-free LDS.128 -> coalesced STG.128 ----
    float4* __restrict__ dst = out4 + tile * 12;
#pragma unroll
    for (int k = 0; k < 12; ++k) {
        int g = t + k * TPB;                 // 0..1535
        int b = g / 12;
        int r = g - b * 12;
        dst[g] = sa4[r * PIT + b];
    }
}

// Tail fallback (batch not a multiple of TPB; unused for BATCH=262144).
__global__ void skeleton_fk_tail(const float* __restrict__ angles,
                                 const float* __restrict__ xyz,
                                 float* __restrict__ out,
                                 int start, int batch)
{
    int b = start + blockIdx.x * blockDim.x + threadIdx.x;
    if (b >= batch) return;
    const float* ab = angles + (size_t)b * (NJ * 6);
    float ref[NJ * 3];
#pragma unroll
    for (int i = 0; i < NJ * 3; ++i) ref[i] = __ldg(xyz + i);

    float Rw[NJ * 9], pw[NJ * 3];
    {
        float a[6];
#pragma unroll
        for (int k = 0; k < 6; ++k) a[k] = ab[k];
        rot6d(a, &Rw[0]);
        float x = ref[0], y = ref[1], z = ref[2];
        pw[0] = Rw[0] * x + Rw[1] * y + Rw[2] * z;
        pw[1] = Rw[3] * x + Rw[4] * y + Rw[5] * z;
        pw[2] = Rw[6] * x + Rw[7] * y + Rw[8] * z;
    }
    constexpr int PARENT[15] = {0, 1, 2, 3, 4, 3, 6, 7, 8, 9, 3, 11, 12, 13, 14};
#pragma unroll
    for (int e = 0; e < 15; ++e) {
        const int p = PARENT[e], c = e + 1;
        float a[6];
#pragma unroll
        for (int k = 0; k < 6; ++k) a[k] = ab[6 * c + k];
        float R[9]; rot6d(a, R);
        float tx = ref[3 * c + 0] - ref[3 * p + 0];
        float ty = ref[3 * c + 1] - ref[3 * p + 1];
        float tz = ref[3 * c + 2] - ref[3 * p + 2];
        const float* pR = &Rw[9 * p];
        float* nR = &Rw[9 * c];
#pragma unroll
        for (int i = 0; i < 3; ++i)
#pragma unroll
            for (int k = 0; k < 3; ++k)
                nR[3 * i + k] = pR[3 * i + 0] * R[k] + pR[3 * i + 1] * R[3 + k]
                              + pR[3 * i + 2] * R[6 + k];
        pw[3 * c + 0] = nR[0] * tx + nR[1] * ty + nR[2] * tz + pw[3 * p + 0];
        pw[3 * c + 1] = nR[3] * tx + nR[4] * ty + nR[5] * tz + pw[3 * p + 1];
        pw[3 * c + 2] = nR[6] * tx + nR[7] * ty + nR[8] * tz + pw[3 * p + 2];
    }
    float* o = out + (size_t)b * (NJ * 3);
#pragma unroll
    for (int i = 0; i < NJ * 3; ++i) o[i] = pw[i];
}

}  // namespace

extern "C" void kernel_launch(void* const* d_in, const int* in_sizes, int n_in,
                              void* d_out, int out_size) {
    const float* angles = (const float*)d_in[0];
    const float* xyz    = (const float*)d_in[1];
    float* out          = (float*)d_out;

    const int batch = in_sizes[0] / (NJ * 6);
    const int full  = batch / TPB;

    cudaFuncSetAttribute(skeleton_fk_v7,
                         cudaFuncAttributeMaxDynamicSharedMemorySize,
                         (int)SMEM_BYTES);

    if (full > 0) {
        skeleton_fk_v7<<<full, TPB, SMEM_BYTES>>>(
            (const float4*)angles, xyz, (float4*)out);
    }
    const int rem = batch - full * TPB;
    if (rem > 0) {
        skeleton_fk_tail<<<(rem + 127) / 128, 128>>>(angles, xyz, out,
                                                     full * TPB, batch);
    }
}